// round 13
// baseline (speedup 1.0000x reference)
#include <cuda_runtime.h>
#include <cuda_bf16.h>
#include <cstdint>

// Problem shapes (fixed by the dataset)
#define BB   8
#define TT   2048
#define DD   1024
#define HH   8
#define SS   128
#define DH   128      // D / H
#define MAXW 32       // max span width
#define NK   (DD/4)   // 256 16-byte chunks per row
#define RPB  32       // rows per logits block
#define RG   4        // rows per group
#define NGRP (RPB/RG) // 8
#define RING 3        // cp.async ring depth (groups) in logits kernel
#define PD   8        // pool cp.async ring depth (rows)

// Scratch: logits for every token, [B*T, H] = 512 KB; decoded spans 8 KB
__device__ float g_logits[BB * TT * HH];
__device__ int2  g_span[BB * SS];

// packed fp32x2 FMA (Blackwell; ptxas never emits it from C++)
#define FMA2(d, a, b, c) \
    asm("fma.rn.f32x2 %0, %1, %2, %3;" : "=l"(d) : "l"(a), "l"(b), "l"(c))

static __device__ __forceinline__ float pairsum(unsigned long long x) {
    float lo, hi;
    asm("mov.b64 {%0, %1}, %2;" : "=f"(lo), "=f"(hi) : "l"(x));
    return lo + hi;
}

// ---------------------------------------------------------------------------
// Kernel 1: logits[row, h] = features[row, :] . key_w[h, :] + key_b[h]
// Thread tid owns 16B chunk tid of D; all 8 heads' keys register-resident.
// Feature rows staged through a 3-deep cp.async smem ring (4 rows/group, 12
// rows in flight). Each thread copies and consumes only its own chunk -> no
// barrier inside the pipeline. Reduction: ONE 31-shfl value-halving
// butterfly per 4 rows. Blocks 0..3 also decode span bounds into g_span.
//
// wait_group discipline: pending at iter g = {g .. min(g+RING-1, NGRP-1)};
// to drain group g the immediate must be (pending_count - 1):
//   g <= NGRP-3 -> 2,  g == NGRP-2 -> 1,  g == NGRP-1 -> 0.
// ---------------------------------------------------------------------------
__global__ __launch_bounds__(256, 2)
void logits_kernel(const float* __restrict__ features,
                   const float* __restrict__ key_w,
                   const float* __restrict__ key_b,
                   const int*   __restrict__ begins32,
                   const int*   __restrict__ ends32)
{
    __shared__ ulonglong2 ring[RING][RG][256];   // 48 KB
    __shared__ float partial[NGRP][8][32];       // 8 KB

    const int tid     = threadIdx.x;
    const int lane    = tid & 31;
    const int wid     = tid >> 5;
    const int rowbase = blockIdx.x * RPB;

    // ---- side task: decode span bounds once for the whole problem.
    // int64-vs-int32 self-detection: genuine int32 ends are >=1 everywhere;
    // int64 high words are zero.
    if (blockIdx.x < 4) {
        const int sp = blockIdx.x * 256 + tid;   // 4*256 = 1024 spans
        bool is64 = (ends32[1] == 0) && (ends32[3] == 0) &&
                    (ends32[5] == 0) && (ends32[7] == 0);
        int begin, end;
        if (is64) { begin = begins32[2 * sp]; end = ends32[2 * sp]; }
        else      { begin = begins32[sp];     end = ends32[sp];     }
        g_span[sp] = make_int2(begin, end - begin);
    }

    // ---- keys for this chunk, all heads, in registers (32 regs)
    const ulonglong2* kw = reinterpret_cast<const ulonglong2*>(key_w);
    ulonglong2 kk[HH];
    #pragma unroll
    for (int h = 0; h < HH; h++) kk[h] = kw[h * NK + tid];

    const char* fbase = reinterpret_cast<const char*>(features)
                        + (size_t)rowbase * (DD * 4) + (size_t)tid * 16;

    // ---- cp.async pipeline
    #define ISSUE_GROUP(g)                                                      \
    do {                                                                        \
        unsigned int _dst = (unsigned int)__cvta_generic_to_shared(             \
                            &ring[(g) % RING][0][tid]);                         \
        _Pragma("unroll")                                                       \
        for (int _r = 0; _r < RG; _r++) {                                       \
            const char* _src = fbase + (size_t)((g) * RG + _r) * (DD * 4);      \
            asm volatile("cp.async.cg.shared.global [%0], [%1], 16;"            \
                         :: "r"(_dst + _r * (256 * 16)), "l"(_src) : "memory"); \
        }                                                                       \
        asm volatile("cp.async.commit_group;" ::: "memory");                    \
    } while (0)

    ISSUE_GROUP(0);
    ISSUE_GROUP(1);
    ISSUE_GROUP(2);

    #pragma unroll
    for (int g = 0; g < NGRP; g++) {
        // drain group g (see header comment for the tail immediates)
        if (g <= NGRP - 3)
            asm volatile("cp.async.wait_group 2;" ::: "memory");
        else if (g == NGRP - 2)
            asm volatile("cp.async.wait_group 1;" ::: "memory");
        else
            asm volatile("cp.async.wait_group 0;" ::: "memory");
        const int buf = g % RING;

        ulonglong2 a[RG];
        #pragma unroll
        for (int r = 0; r < RG; r++) a[r] = ring[buf][r][tid];

        // refill this slot (LDS above already issued; async data lands later)
        if (g + RING < NGRP) ISSUE_GROUP(g + RING);

        unsigned long long acc[HH][RG];
        #pragma unroll
        for (int h = 0; h < HH; h++)
            #pragma unroll
            for (int r = 0; r < RG; r++) acc[h][r] = 0ull;

        #pragma unroll
        for (int h = 0; h < HH; h++) {
            #pragma unroll
            for (int r = 0; r < RG; r++) {
                FMA2(acc[h][r], a[r].x, kk[h].x, acc[h][r]);
                FMA2(acc[h][r], a[r].y, kk[h].y, acc[h][r]);
            }
        }

        // v[idx], idx = h*4 + r  (32 values across 32 lanes)
        float v[32];
        #pragma unroll
        for (int h = 0; h < HH; h++)
            #pragma unroll
            for (int r = 0; r < RG; r++)
                v[h * 4 + r] = pairsum(acc[h][r]);

        // value-halving butterfly: after masks 16,8,4,2,1, lane l holds the
        // warp-total of v_orig[l].
        #pragma unroll
        for (int m = 16; m >= 1; m >>= 1) {
            const bool up = (lane & m) != 0;
            #pragma unroll
            for (int i = 0; i < 16; i++) {
                if (i < m) {
                    float send = up ? v[i] : v[i + m];
                    float recv = __shfl_xor_sync(0xffffffffu, send, m);
                    v[i] = (up ? v[i + m] : v[i]) + recv;
                }
            }
        }
        partial[g][wid][lane] = v[0];
    }
    __syncthreads();

    // final combine: 256 threads, one (group, idx) each; sum the 8 warps
    {
        const int g   = tid >> 5;
        const int idx = tid & 31;
        const int h   = idx >> 2;
        const int r   = idx & 3;
        float s = 0.f;
        #pragma unroll
        for (int wq = 0; wq < 8; wq++) s += partial[g][wq][idx];
        g_logits[(size_t)(rowbase + g * RG + r) * HH + h] = s + key_b[h];
    }
    #undef ISSUE_GROUP
}

// ---------------------------------------------------------------------------
// Kernel 2: per (b,s) pooling with a cp.async smem ring (8 rows in flight,
// one commit-group per row, each thread touches only its own 16B slot ->
// barrier-free). ~30 regs + 32 KB smem -> ~7 CTAs/SM, much deeper aggregate
// MLP than the register double-buffer. Softmax overlaps the first 8 rows.
// Rows >= w clamp to w-1 (L1 hits); their weights are exactly 0.
// Steady state: 8 groups always pending, wait_group 7 drains the row being
// consumed, slot refilled immediately after the LDS.
// ---------------------------------------------------------------------------
__global__ __launch_bounds__(256)
void pool_kernel(const float* __restrict__ features,
                 float*       __restrict__ out)
{
    __shared__ float4 ring[PD][256];   // 32 KB

    const int tid  = threadIdx.x;
    const int lane = tid & 31;
    const int wid  = tid >> 5;
    const int blk  = blockIdx.x;      // b*S + s
    const int b    = blk >> 7;

    const int2 se   = g_span[blk];
    const int begin = se.x;
    const int w     = se.y;                          // 1..32
    const int wm1   = w - 1;

    const char* fbase = reinterpret_cast<const char*>(features)
                        + (size_t)(b * TT + begin) * (DD * 4) + (size_t)tid * 16;
    const unsigned int sbase =
        (unsigned int)__cvta_generic_to_shared(&ring[0][tid]);

    // issue PD row-groups up front (clamped rows are L1 hits)
    #pragma unroll
    for (int j = 0; j < PD; j++) {
        const char* src = fbase + (size_t)min(j, wm1) * (DD * 4);
        asm volatile("cp.async.cg.shared.global [%0], [%1], 16;"
                     :: "r"(sbase + (unsigned)(j * 256 * 16)), "l"(src)
                     : "memory");
        asm volatile("cp.async.commit_group;" ::: "memory");
    }

    // per-warp softmax for head h = wid; lane = t (overlaps in-flight copies)
    const int h = wid;
    float v = (lane < w)
            ? g_logits[((size_t)b * TT + begin + lane) * HH + h]
            : -3.0e38f;
    float m = v;
    m = fmaxf(m, __shfl_xor_sync(0xffffffffu, m, 16));
    m = fmaxf(m, __shfl_xor_sync(0xffffffffu, m, 8));
    m = fmaxf(m, __shfl_xor_sync(0xffffffffu, m, 4));
    m = fmaxf(m, __shfl_xor_sync(0xffffffffu, m, 2));
    m = fmaxf(m, __shfl_xor_sync(0xffffffffu, m, 1));
    float e = (lane < w) ? __expf(v - m) : 0.f;
    float s = e;
    s += __shfl_xor_sync(0xffffffffu, s, 16);
    s += __shfl_xor_sync(0xffffffffu, s, 8);
    s += __shfl_xor_sync(0xffffffffu, s, 4);
    s += __shfl_xor_sync(0xffffffffu, s, 2);
    s += __shfl_xor_sync(0xffffffffu, s, 1);
    const float wval = e * (1.f / s);                // 0 for lanes >= w

    // ring-consume loop: always PD groups pending -> wait_group PD-1 drains
    // exactly row t; refill slot immediately (thread-private slot, no barrier).
    float4 o = make_float4(0.f, 0.f, 0.f, 0.f);
    for (int t = 0; t < w; t++) {
        asm volatile("cp.async.wait_group %0;" :: "n"(PD - 1) : "memory");
        const int slot = t & (PD - 1);
        float4 f = ring[slot][tid];
        const char* src = fbase + (size_t)min(t + PD, wm1) * (DD * 4);
        asm volatile("cp.async.cg.shared.global [%0], [%1], 16;"
                     :: "r"(sbase + (unsigned)(slot * 256 * 16)), "l"(src)
                     : "memory");
        asm volatile("cp.async.commit_group;" ::: "memory");
        float wt = __shfl_sync(0xffffffffu, wval, t);
        o.x = fmaf(wt, f.x, o.x);
        o.y = fmaf(wt, f.y, o.y);
        o.z = fmaf(wt, f.z, o.z);
        o.w = fmaf(wt, f.w, o.w);
    }
    reinterpret_cast<float4*>(out)[(size_t)blk * NK + tid] = o;

    // drain leftover async copies before block exit (writes go to our smem)
    asm volatile("cp.async.wait_group 0;" ::: "memory");
}

extern "C" void kernel_launch(void* const* d_in, const int* in_sizes, int n_in,
                              void* d_out, int out_size)
{
    const float* features = (const float*)d_in[0];  // [B,T,D] f32
    const int*   begins   = (const int*)  d_in[1];  // [B,S] int32/int64 (self-detected)
    const int*   ends     = (const int*)  d_in[2];
    const float* key_w    = (const float*)d_in[3];  // [H,D] f32
    const float* key_b    = (const float*)d_in[4];  // [H]   f32
    float*       out      = (float*)d_out;          // [B,S,D] f32

    logits_kernel<<<(BB * TT) / RPB, 256>>>(features, key_w, key_b, begins, ends);
    pool_kernel<<<BB * SS, 256>>>(features, out);
}